// round 2
// baseline (speedup 1.0000x reference)
#include <cuda_runtime.h>
#include <cuda_bf16.h>
#include <cstdint>
#include <math.h>

#define PX       48
#define PTOT     110592            // 48^3
#define NDIR     32
#define NRES     64
#define PCHUNK   384
#define NBLOCKS  (PTOT / PCHUNK)   // 288
#define NE       (4 * NDIR * NRES) // (b*2+c) in {0..3} -> 8192 floats

// ---------------- device scratch (static; no allocations) -------------------
__device__ float      g_dirs[3 * NDIR];   // [3][32]
__device__ float      g_K[NRES];          // exp(-8*lin_r)
__device__ float      g_E[NE];            // [(b*2+c)][d][r]
__device__ int        g_tgt64;            // 1 if target is int64
__device__ ulonglong2 g_dw[PTOT];         // .x = pack(dw[b0,c0],dw[b1,c0]), .y = c1

// ---------------- small asm helpers -----------------------------------------
__device__ __forceinline__ unsigned long long pack2(float lo, float hi) {
    unsigned long long r;
    asm("mov.b64 %0, {%1, %2};" : "=l"(r) : "f"(lo), "f"(hi));
    return r;
}
__device__ __forceinline__ void unpack2(unsigned long long v, float& lo, float& hi) {
    asm("mov.b64 {%0, %1}, %2;" : "=f"(lo), "=f"(hi) : "l"(v));
}
__device__ __forceinline__ void fma2(unsigned long long& acc, unsigned long long ab,
                                     unsigned long long c) {
    asm("fma.rn.f32x2 %0, %1, %2, %0;" : "+l"(acc) : "l"(ab), "l"(c));
}
__device__ __forceinline__ float rcp_approx(float x) {
    float r;
    asm("rcp.approx.f32 %0, %1;" : "=f"(r) : "f"(x));
    return r;
}

// ---------------- threefry2x32 (JAX) ----------------------------------------
__device__ __forceinline__ uint32_t rotl32(uint32_t x, int d) {
    return (x << d) | (x >> (32 - d));
}
__device__ void threefry2x32(uint32_t k0, uint32_t k1, uint32_t& x0, uint32_t& x1) {
    uint32_t k2 = k0 ^ k1 ^ 0x1BD11BDAu;
    x0 += k0; x1 += k1;
#define TFR(r) { x0 += x1; x1 = rotl32(x1, r); x1 ^= x0; }
    TFR(13) TFR(15) TFR(26) TFR(6)
    x0 += k1; x1 += k2 + 1u;
    TFR(17) TFR(29) TFR(16) TFR(24)
    x0 += k2; x1 += k0 + 2u;
    TFR(13) TFR(15) TFR(26) TFR(6)
    x0 += k0; x1 += k1 + 3u;
    TFR(17) TFR(29) TFR(16) TFR(24)
    x0 += k1; x1 += k2 + 4u;
    TFR(13) TFR(15) TFR(26) TFR(6)
    x0 += k2; x1 += k0 + 5u;
#undef TFR
}

// XLA/Giles f32 erfinv
__device__ float erfinv_f32(float x) {
    float w = -log1pf(-x * x);
    float p;
    if (w < 5.0f) {
        w = w - 2.5f;
        p =            2.81022636e-08f;
        p = fmaf(p, w, 3.43273939e-07f);
        p = fmaf(p, w, -3.5233877e-06f);
        p = fmaf(p, w, -4.39150654e-06f);
        p = fmaf(p, w, 0.00021858087f);
        p = fmaf(p, w, -0.00125372503f);
        p = fmaf(p, w, -0.00417768164f);
        p = fmaf(p, w, 0.246640727f);
        p = fmaf(p, w, 1.50140941f);
    } else {
        w = sqrtf(w) - 3.0f;
        p =            -0.000200214257f;
        p = fmaf(p, w, 0.000100950558f);
        p = fmaf(p, w, 0.00134934322f);
        p = fmaf(p, w, -0.00367342844f);
        p = fmaf(p, w, 0.00573950773f);
        p = fmaf(p, w, -0.0076224613f);
        p = fmaf(p, w, 0.00943887047f);
        p = fmaf(p, w, 1.00167406f);
        p = fmaf(p, w, 2.83297682f);
    }
    return p * x;
}

// ---------------- kernel 0: init (zero E, dirs, K table, dtype sniff) -------
__global__ void init_kernel(const void* __restrict__ tgt) {
    int t = threadIdx.x;  // 128 threads

    for (int i = t; i < NE; i += 128) g_E[i] = 0.0f;

    if (t == 0) {
        // int64 targets (values 0..2, little-endian) have all-zero odd words
        const int* ti = (const int*)tgt;
        int all0 = 1;
        for (int q = 0; q < 64; q++)
            if (ti[2 * q + 1] != 0) { all0 = 0; break; }
        g_tgt64 = all0;
    }

    __shared__ float sv[96];
    if (t < 96) {
        // jax partitionable threefry: counter = uint64 iota -> (hi=0, lo=i),
        // 32-bit output = o0 ^ o1; key = (0, 17)
        uint32_t x0 = 0u, x1 = (uint32_t)t;
        threefry2x32(0u, 17u, x0, x1);
        uint32_t bits = x0 ^ x1;
        float f = __uint_as_float((bits >> 9) | 0x3f800000u) - 1.0f;  // [0,1)
        const float lo = -0.99999994f;  // nextafterf(-1, 0)
        float u = __fadd_rn(__fmul_rn(f, 2.0f), lo);  // span rounds to 2.0f
        u = fmaxf(u, lo);
        sv[t] = 1.41421356237f * erfinv_f32(u);
    }
    __syncthreads();
    if (t < NDIR) {
        float a = sv[t], b = sv[NDIR + t], c = sv[2 * NDIR + t];
        float n = sqrtf(a * a + b * b + c * c);
        n = fmaxf(n, 1e-12f);
        g_dirs[t]            = a / n;
        g_dirs[NDIR + t]     = b / n;
        g_dirs[2 * NDIR + t] = c / n;
    }
    if (t < NRES) {
        float radius = 1.1f * sqrtf(3.0f);
        double step = (2.0 * (double)radius) / 63.0;
        double lin = -(double)radius + (double)t * step;
        g_K[t] = (float)exp(-8.0 * lin);
    }
}

// ---------------- kernel 1: prep (softmax - onehot, packed) -----------------
__global__ __launch_bounds__(256) void prep_kernel(const float* __restrict__ pred,
                                                   const void* __restrict__ tgt) {
    int p = blockIdx.x * 256 + threadIdx.x;
    if (p >= PTOT) return;
    int t64 = g_tgt64;

    float dw[2][2];
#pragma unroll
    for (int b = 0; b < 2; b++) {
        float x0 = pred[(b * 3 + 0) * PTOT + p];
        float x1 = pred[(b * 3 + 1) * PTOT + p];
        float x2 = pred[(b * 3 + 2) * PTOT + p];
        float m = fmaxf(x0, fmaxf(x1, x2));
        float e0 = expf(x0 - m), e1 = expf(x1 - m), e2 = expf(x2 - m);
        float s = e0 + e1 + e2;
        float w0 = e0 / s, w1 = e1 / s;
        int tv;
        if (t64) tv = (int)((const long long*)tgt)[b * PTOT + p];
        else     tv = ((const int*)tgt)[b * PTOT + p];
        dw[b][0] = w0 - (tv == 0 ? 1.0f : 0.0f);
        dw[b][1] = w1 - (tv == 1 ? 1.0f : 0.0f);
    }
    ulonglong2 out;
    out.x = pack2(dw[0][0], dw[1][0]);
    out.y = pack2(dw[0][1], dw[1][1]);
    g_dw[p] = out;
}

// ---------------- kernel 2: main accumulation -------------------------------
// block = 384-p chunk; warp w owns r in [w*8, w*8+8); lane = direction
__global__ __launch_bounds__(256) void main_kernel() {
    __shared__ ulonglong2 s_dw[PCHUNK];

    int tid = threadIdx.x;
    int lane = tid & 31;
    int w = tid >> 5;
    int pbase = blockIdx.x * PCHUNK;

    for (int i = tid; i < PCHUNK; i += 256) s_dw[i] = g_dw[pbase + i];
    __syncthreads();

    float d0 = g_dirs[lane];
    float d1 = g_dirs[NDIR + lane];
    float d2 = g_dirs[2 * NDIR + lane];

    float K[8];
#pragma unroll
    for (int k = 0; k < 8; k++) K[k] = g_K[w * 8 + k];

    unsigned long long accA[8], accB[8];
#pragma unroll
    for (int k = 0; k < 8; k++) { accA[k] = 0ull; accB[k] = 0ull; }

    const float CSTEP = 2.0f / 47.0f;

    for (int i = 0; i < PCHUNK; i++) {
        int p = pbase + i;
        int ix = p / 2304;
        int rem = p - ix * 2304;
        int iy = rem / 48;
        int iz = rem - iy * 48;
        float cx = fmaf((float)ix, CSTEP, -1.0f);
        float cy = fmaf((float)iy, CSTEP, -1.0f);
        float cz = fmaf((float)iz, CSTEP, -1.0f);

        float nh = cx * d0;
        nh = fmaf(cy, d1, nh);
        nh = fmaf(cz, d2, nh);
        float eb = __expf(8.0f * nh);   // exp(8*nh)

        ulonglong2 dw = s_dw[i];
#pragma unroll
        for (int k = 0; k < 8; k++) {
            float e = eb * K[k];
            float t = 1.0f + e;
            float s = rcp_approx(t);        // sigmoid(8*(lin_r - nh))
            unsigned long long s2 = pack2(s, s);
            fma2(accA[k], dw.x, s2);        // (b0,c0),(b1,c0)
            fma2(accB[k], dw.y, s2);        // (b0,c1),(b1,c1)
        }
    }

    // flush: g_E[(b*2+c)][d][r]
#pragma unroll
    for (int k = 0; k < 8; k++) {
        int r = w * 8 + k;
        float a0, a1, b0, b1;
        unpack2(accA[k], a0, a1);
        unpack2(accB[k], b0, b1);
        atomicAdd(&g_E[(0 * NDIR + lane) * NRES + r], a0);  // b0,c0
        atomicAdd(&g_E[(2 * NDIR + lane) * NRES + r], a1);  // b1,c0
        atomicAdd(&g_E[(1 * NDIR + lane) * NRES + r], b0);  // b0,c1
        atomicAdd(&g_E[(3 * NDIR + lane) * NRES + r], b1);  // b1,c1
    }
}

// ---------------- kernel 3: final loss ---------------------------------------
__global__ __launch_bounds__(256) void final_kernel(float* __restrict__ out) {
    int tid = threadIdx.x;
    float sum = 0.0f;
    // idx over (b, d*64+r): 2 * 2048 = 4096
    for (int idx = tid; idx < 4096; idx += 256) {
        int b = idx >> 11;
        int dr = idx & 2047;
        float e0 = g_E[(b * 2 + 0) * 2048 + dr];
        float e1 = g_E[(b * 2 + 1) * 2048 + dr];
        float e2 = -(e0 + e1);
        sum += e0 * e0 + e1 * e1 + e2 * e2;
    }
    // block reduce
    __shared__ float red[8];
#pragma unroll
    for (int off = 16; off > 0; off >>= 1)
        sum += __shfl_down_sync(0xFFFFFFFFu, sum, off);
    if ((tid & 31) == 0) red[tid >> 5] = sum;
    __syncthreads();
    if (tid < 8) {
        float v = red[tid];
#pragma unroll
        for (int off = 4; off > 0; off >>= 1)
            v += __shfl_down_sync(0xFFu, v, off);
        if (tid == 0) out[0] = v / 12288.0f;
    }
}

// ---------------- launcher ----------------------------------------------------
extern "C" void kernel_launch(void* const* d_in, const int* in_sizes, int n_in,
                              void* d_out, int out_size) {
    const float* pred = (const float*)d_in[0];
    const void*  tgt  = d_in[1];
    float* out = (float*)d_out;
    (void)in_sizes; (void)n_in; (void)out_size;

    init_kernel<<<1, 128>>>(tgt);
    prep_kernel<<<PTOT / 256, 256>>>(pred, tgt);
    main_kernel<<<NBLOCKS, 256>>>();
    final_kernel<<<1, 256>>>(out);
}